// round 8
// baseline (speedup 1.0000x reference)
#include <cuda_runtime.h>
#include <math.h>

// 21-qubit / 3-layer QNN statevector sim. State in "pair format":
//   d_state[h] = float4(re(2h), re(2h+1), im(2h), im(2h+1)),  h = 20-bit pair idx.
// amp bit k <-> qubit (20-k); amp bit 0 = float4 lane; pair bit k = amp bit k+1.
// passA: Rot amps 0..11 + CNOT targets 0..9 (perm + lane swap folded into store).
//        tile = pair bits 0..10 (2048 pairs), 256 thr x 8 pairs, grid 512, 1 wave.
// passB: Rot amps 12..20 + CNOT targets 10..19 (perm folded into store).
//        tile = pair bits 9..19 (2048 pairs), 256 thr x 8 pairs, grid 512, 1 wave.
// All smem access patterns keep lane bits in l0..4 -> conflict-free, no swizzle.

#define NQ      21
#define NPAIR   (1u << 20)
#define THREADS 256
#define TILEP   2048
#define SMEMB   (TILEP * 16 + 768)
#define NBLK    512

typedef unsigned long long u64;

__device__ float4 d_state[NPAIR];

struct Gate2 { u64 p, q, mq, r, mr, s, ms; };
__device__ Gate2 d_gates[3][NQ];
struct Gate0 { u64 v[6]; };            // (p,p)(r,-r)(-q,q)(-s,-s)(q,-q)(s,s)
__device__ Gate0 d_gate0[3];

__device__ __forceinline__ u64 fma2(u64 a, u64 b, u64 c) {
    u64 d; asm("fma.rn.f32x2 %0,%1,%2,%3;" : "=l"(d) : "l"(a), "l"(b), "l"(c)); return d;
}
__device__ __forceinline__ u64 mul2(u64 a, u64 b) {
    u64 d; asm("mul.rn.f32x2 %0,%1,%2;" : "=l"(d) : "l"(a), "l"(b)); return d;
}
__device__ __forceinline__ float flo(u64 v) { return __uint_as_float((unsigned)v); }
__device__ __forceinline__ float fhi(u64 v) { return __uint_as_float((unsigned)(v >> 32)); }
__device__ __forceinline__ u64 fpack(float a, float b) {
    return (u64)__float_as_uint(a) | ((u64)__float_as_uint(b) << 32);
}
__device__ __forceinline__ u64 swap64(u64 v) { return (v >> 32) | (v << 32); }

__global__ void prep_gates(const float* __restrict__ param, float* __restrict__ out) {
    int t = threadIdx.x;
    if (t == 0) out[0] = 0.f;
    if (t >= 3 * NQ) return;
    int layer = t / NQ, bit = t % NQ, qubit = 20 - bit;
    const float* pp = param + (layer * NQ + qubit) * 3;
    float phi = pp[0], th = pp[1], om = pp[2];
    float s, c;   sincosf(0.5f * th, &s, &c);
    float sa, ca; sincosf(0.5f * (phi + om), &sa, &ca);
    float sb, cb; sincosf(0.5f * (phi - om), &sb, &cb);
    // u00=(p,q)  u01=(r,s)  u10=(-r,s)  u11=(p,-q)
    float p = ca * c, q = -sa * c, r = -cb * s, sv = -sb * s;
    Gate2 g;
    g.p  = fpack(p, p);    g.q  = fpack(q, q);   g.mq = fpack(-q, -q);
    g.r  = fpack(r, r);    g.mr = fpack(-r, -r);
    g.s  = fpack(sv, sv);  g.ms = fpack(-sv, -sv);
    d_gates[layer][bit] = g;
    if (bit == 0) {
        Gate0 g0;
        g0.v[0] = fpack(p, p);    g0.v[1] = fpack(r, -r);
        g0.v[2] = fpack(-q, q);   g0.v[3] = fpack(-sv, -sv);
        g0.v[4] = fpack(q, -q);   g0.v[5] = fpack(sv, sv);
        d_gate0[layer] = g0;
    }
}

// Paired-register gate on register-index bit S.
template<int S, int N>
__device__ __forceinline__ void vgate(u64 (&re)[N], u64 (&im)[N], const u64* __restrict__ g) {
    const u64 p = g[0], q = g[1], mq = g[2], r = g[3], mr = g[4], s = g[5], ms = g[6];
#pragma unroll
    for (int j = 0; j < N; j++) {
        if (j & S) continue;
        const int j1 = j | S;
        u64 xr = re[j], xi = im[j], yr = re[j1], yi = im[j1];
        u64 nr0 = fma2(ms, yi, fma2(r,  yr, fma2(mq, xi, mul2(p,  xr))));
        u64 ni0 = fma2(r,  yi, fma2(s,  yr, fma2(p,  xi, mul2(q,  xr))));
        u64 nr1 = fma2(q,  yi, fma2(p,  yr, fma2(ms, xi, mul2(mr, xr))));
        u64 ni1 = fma2(p,  yi, fma2(mq, yr, fma2(mr, xi, mul2(s,  xr))));
        re[j] = nr0; im[j] = ni0; re[j1] = nr1; im[j1] = ni1;
    }
}

// Warp-shuffle gate on lane bit B of threadIdx.
template<int B, int N>
__device__ __forceinline__ void hgate(u64 (&re)[N], u64 (&im)[N], const u64* __restrict__ g) {
    const u64 p = g[0], s = g[5], ms = g[6];
    const bool hi = (threadIdx.x >> B) & 1;
    const u64 A  = hi ? g[1] : g[2];   //  q : -q
    const u64 C  = hi ? g[2] : g[1];   // -q :  q
    const u64 Bc = hi ? g[4] : g[3];   // -r :  r
#pragma unroll
    for (int j = 0; j < N; j++) {
        u64 wr = __shfl_xor_sync(0xffffffffu, re[j], 1 << B);
        u64 wi = __shfl_xor_sync(0xffffffffu, im[j], 1 << B);
        u64 nr = fma2(ms, wi, fma2(Bc, wr, fma2(A, im[j], mul2(p, re[j]))));
        u64 ni = fma2(Bc, wi, fma2(s,  wr, fma2(p, im[j], mul2(C, re[j]))));
        re[j] = nr; im[j] = ni;
    }
}

// In-lane (amp bit 0) gate via packed f32x2 with mixed-sign coefficient pairs.
template<int N>
__device__ __forceinline__ void sgate2(u64 (&re)[N], u64 (&im)[N], const u64* __restrict__ g) {
    const u64 pp = g[0], rmr = g[1], mqq = g[2], msms = g[3], qmq = g[4], ss = g[5];
#pragma unroll
    for (int j = 0; j < N; j++) {
        u64 sre = swap64(re[j]), sim = swap64(im[j]);
        u64 nr = fma2(msms, sim, fma2(mqq, im[j], fma2(rmr, sre, mul2(pp,  re[j]))));
        u64 ni = fma2(rmr,  sim, fma2(pp,  im[j], fma2(ss,  sre, mul2(qmq, re[j]))));
        re[j] = nr; im[j] = ni;
    }
}

__device__ __forceinline__ float4 packf4(u64 r, u64 i) {
    return make_float4(flo(r), fhi(r), flo(i), fhi(i));
}
__device__ __forceinline__ void unpackf4(float4 v, u64& r, u64& i) {
    r = fpack(v.x, v.y); i = fpack(v.z, v.w);
}

// r2 layout (both passes): l = t0..4 | j<<5 | t5..7<<8  (lanes stay in l0..4)
__device__ __forceinline__ unsigned r2i(unsigned t, unsigned j) {
    return (t & 31u) | (j << 5) | ((t >> 5) << 8);
}

// ============================ pass A ============================
// tile = pair bits 0..10 (amps 0..11); gp = blk<<11.
template<int LAYER, bool FIRST>
__global__ void __launch_bounds__(THREADS, 4)
passA_kernel(const float* __restrict__ feat) {
    extern __shared__ char smraw[];
    float4* sm = reinterpret_cast<float4*>(smraw);
    u64* gsm = reinterpret_cast<u64*>(smraw + TILEP * 16);
    const unsigned t  = threadIdx.x;
    const unsigned gp = blockIdx.x << 11;
    u64 re[8], im[8];

    // stage gates: [0..5] = gate0 (amp0), [6 + (a-1)*7] = amps 1..11
    if (t < 6)  gsm[t] = reinterpret_cast<const u64*>(&d_gate0[LAYER])[t];
    if (t < 77) gsm[6 + t] = reinterpret_cast<const u64*>(&d_gates[LAYER][1])[t];

    // r1: l = t | (j<<8); lanes = pairs 0..4 (amps 1..5), j = pairs 8..10 (amps 9..11)
#pragma unroll
    for (int j = 0; j < 8; j++) {
        unsigned l = t | (j << 8);
        if (FIRST) {
            float2 fv = reinterpret_cast<const float2*>(feat)[gp | l];
            re[j] = fpack(fv.x, fv.y); im[j] = 0ull;
        } else {
            unpackf4(d_state[gp | l], re[j], im[j]);
        }
    }
    __syncthreads();                      // gate table visible

    sgate2(re, im, gsm);                  // amp 0
    hgate<0>(re, im, gsm + 6);            // amp 1
    hgate<1>(re, im, gsm + 13);           // amp 2
    hgate<2>(re, im, gsm + 20);           // amp 3
    hgate<3>(re, im, gsm + 27);           // amp 4
    hgate<4>(re, im, gsm + 34);           // amp 5
    vgate<1>(re, im, gsm + 62);           // amp 9  (pair 8 = j bit 0)
    vgate<2>(re, im, gsm + 69);           // amp 10
    vgate<4>(re, im, gsm + 76);           // amp 11
#pragma unroll
    for (int j = 0; j < 8; j++) sm[t | (j << 8)] = packf4(re[j], im[j]);
    __syncthreads();

    // r2: j = pairs 5..7 (amps 6..8)
#pragma unroll
    for (int j = 0; j < 8; j++) unpackf4(sm[r2i(t, j)], re[j], im[j]);
    vgate<1>(re, im, gsm + 41);           // amp 6
    vgate<2>(re, im, gsm + 48);           // amp 7
    vgate<4>(re, im, gsm + 55);           // amp 8

    // CNOT perm (targets amps 0..9) inverse-folded into store + lane swap
#pragma unroll
    for (int j = 0; j < 8; j++) {
        unsigned l = r2i(t, j);
        unsigned u = l ^ ((l >> 1) & 0x155u);
        unsigned h = u ^ ((u >> 1) & 0xAAu);
        float4 v = packf4(re[j], im[j]);
        d_state[gp | h] = (h & 1u) ? make_float4(v.y, v.x, v.w, v.z) : v;
    }
}

// ============================ pass B ============================
// tile = pair bits 9..19 (amps 10..20); g = blk | (l<<9), blk = pair bits 0..8.
template<int LAYER, bool LAST>
__global__ void __launch_bounds__(THREADS, 4)
passB_kernel(float* __restrict__ out) {
    extern __shared__ char smraw[];
    float4* sm = reinterpret_cast<float4*>(smraw);
    u64* gsm = reinterpret_cast<u64*>(smraw + TILEP * 16);
    const unsigned t = threadIdx.x;
    const unsigned blk = blockIdx.x;
    u64 re[8], im[8];

    // stage gates: amps 12..20 at [(a-12)*7]
    if (t < 63) gsm[t] = reinterpret_cast<const u64*>(&d_gates[LAYER][12])[t];

    // r1: l = t | (j<<8); lanes = locals 0..4 (amps 10..14), j = locals 8..10 (amps 18..20)
#pragma unroll
    for (int j = 0; j < 8; j++) {
        unsigned l = t | (j << 8);
        unpackf4(d_state[blk | (l << 9)], re[j], im[j]);
    }
    __syncthreads();                      // gate table visible

    hgate<2>(re, im, gsm + 0);            // amp 12 (local 2)
    hgate<3>(re, im, gsm + 7);            // amp 13
    hgate<4>(re, im, gsm + 14);           // amp 14
    vgate<1>(re, im, gsm + 42);           // amp 18 (local 8 = j bit 0)
    vgate<2>(re, im, gsm + 49);           // amp 19
    vgate<4>(re, im, gsm + 56);           // amp 20
#pragma unroll
    for (int j = 0; j < 8; j++) sm[t | (j << 8)] = packf4(re[j], im[j]);
    __syncthreads();

    // r2: j = locals 5..7 (amps 15..17)
#pragma unroll
    for (int j = 0; j < 8; j++) unpackf4(sm[r2i(t, j)], re[j], im[j]);
    vgate<1>(re, im, gsm + 21);           // amp 15
    vgate<2>(re, im, gsm + 28);           // amp 16
    vgate<4>(re, im, gsm + 35);           // amp 17

    if (LAST) {
        // Final CNOT perm is a bijection preserving amp bit 0 -> skip; sum lo lanes.
        float acc = 0.f;
#pragma unroll
        for (int j = 0; j < 8; j++) {
            float rr = flo(re[j]), ii = flo(im[j]);
            acc += rr * rr + ii * ii;
        }
#pragma unroll
        for (int o = 16; o > 0; o >>= 1)
            acc += __shfl_xor_sync(0xffffffffu, acc, o);
        __syncthreads();
        float* red = reinterpret_cast<float*>(sm);
        if ((t & 31u) == 0) red[t >> 5] = acc;
        __syncthreads();
        if (t == 0) {
            float v = 0.f;
#pragma unroll
            for (int w = 0; w < THREADS / 32; w++) v += red[w];
            atomicAdd(out, v);
        }
        return;
    }

    // CNOT perm (targets amps 10..19 = locals 0..9) inverse-folded into store
#pragma unroll
    for (int j = 0; j < 8; j++) {
        unsigned l = r2i(t, j);
        unsigned u = l ^ ((l >> 1) & 0x2AAu);
        unsigned h = u ^ ((u >> 1) & 0x155u);
        d_state[blk | (h << 9)] = packf4(re[j], im[j]);
    }
}

extern "C" void kernel_launch(void* const* d_in, const int* in_sizes, int n_in,
                              void* d_out, int out_size) {
    const float* feat  = (const float*)d_in[0];
    const float* param = (const float*)d_in[1];
    float* out = (float*)d_out;

    cudaFuncSetAttribute(passA_kernel<0, true >, cudaFuncAttributeMaxDynamicSharedMemorySize, SMEMB);
    cudaFuncSetAttribute(passA_kernel<1, false>, cudaFuncAttributeMaxDynamicSharedMemorySize, SMEMB);
    cudaFuncSetAttribute(passA_kernel<2, false>, cudaFuncAttributeMaxDynamicSharedMemorySize, SMEMB);
    cudaFuncSetAttribute(passB_kernel<0, false>, cudaFuncAttributeMaxDynamicSharedMemorySize, SMEMB);
    cudaFuncSetAttribute(passB_kernel<1, false>, cudaFuncAttributeMaxDynamicSharedMemorySize, SMEMB);
    cudaFuncSetAttribute(passB_kernel<2, true >, cudaFuncAttributeMaxDynamicSharedMemorySize, SMEMB);

    prep_gates<<<1, 64>>>(param, out);
    passA_kernel<0, true ><<<NBLK, THREADS, SMEMB>>>(feat);
    passB_kernel<0, false><<<NBLK, THREADS, SMEMB>>>(out);
    passA_kernel<1, false><<<NBLK, THREADS, SMEMB>>>(feat);
    passB_kernel<1, false><<<NBLK, THREADS, SMEMB>>>(out);
    passA_kernel<2, false><<<NBLK, THREADS, SMEMB>>>(feat);
    passB_kernel<2, true ><<<NBLK, THREADS, SMEMB>>>(out);
}